// round 14
// baseline (speedup 1.0000x reference)
#include <cuda_runtime.h>
#include <cuda_fp16.h>
#include <cstdint>

// ---------------------------------------------------------------------------
// MeshRefineNet on GB300 (sm_103a), R14 = R13 (777.3us) with L1-pressure cuts:
//   * gemm tiles 128 rows, warp grid 4x4, warp tile 32x64 (LDSM/MMA -25%)
//   * feat converted to fp16 once (prep_feat) -> all layers use fp16 A path
//   * gemm0 kept at launch index 3 for ncu attribution
//   layer i: h0 = x@W0+b0; h1 = x@W1+b1; out = h0 + sum_{j in N(i)} h1[j]
//   relu after layers 0..2; skip before layer 3; layer 3 dout=3.
// fp16 intermediates, fp32 accumulation (rel err ~2.3e-4, thr 1e-3).
// ---------------------------------------------------------------------------

#define NMAX 320000
#define EMAX 1000000

__device__ __align__(16) __half g_feat16[NMAX * 128];
__device__ __align__(16) __half g_bufA[NMAX * 128];
__device__ __align__(16) __half g_bufB[NMAX * 128];
__device__ __align__(16) __half g_h1 [NMAX * 128];
__device__ float g_h1s[NMAX * 3];

__device__ __align__(16) __half g_W16[3][256 * 128];
__device__ float g_bias[3][256];

__device__ int g_deg[NMAX];
__device__ int g_cur[NMAX];
__device__ int g_rowstart[NMAX + 1];
__device__ int g_adj[2 * EMAX];
__device__ int g_bsum[512];

// ======================= helpers ===========================================
__device__ __forceinline__ uint32_t smem_to_u32(const void* p) {
    uint32_t a;
    asm("{ .reg .u64 t; cvta.to.shared.u64 t, %1; cvt.u32.u64 %0, t; }"
        : "=r"(a) : "l"(p));
    return a;
}
__device__ __forceinline__ uint32_t pkh(float a, float b) {
    __half2 t = __floats2half2_rn(a, b);
    return *(uint32_t*)&t;
}
__device__ __forceinline__ float2 uph(uint32_t u) {
    __half2 h = *(__half2*)&u;
    return __half22float2(h);
}
__device__ __forceinline__ float4 h4tof4(uint2 u) {
    float2 a = uph(u.x), b = uph(u.y);
    return make_float4(a.x, a.y, b.x, b.y);
}
__device__ __forceinline__ uint2 f4toh4(float4 v) {
    uint2 u;
    u.x = pkh(v.x, v.y);
    u.y = pkh(v.z, v.w);
    return u;
}
__device__ __forceinline__ uint32_t relu_h2(uint32_t u) {
    __half2 h = *(__half2*)&u;
    __half2 z = __floats2half2_rn(0.f, 0.f);
    h = __hmax2(h, z);
    return *(uint32_t*)&h;
}
// XOR-swizzled offset for 16-bit tile images with 256B rows (128 halves/row).
__device__ __forceinline__ uint32_t aswz(uint32_t row, uint32_t kblk) {
    return row * 256u + ((((kblk ^ row) & 7u) | (kblk & 8u)) << 4);
}
__device__ __forceinline__ void ldsm_x4(uint32_t& r0, uint32_t& r1,
                                        uint32_t& r2, uint32_t& r3, uint32_t addr) {
    asm volatile("ldmatrix.sync.aligned.m8n8.x4.shared.b16 {%0,%1,%2,%3}, [%4];"
                 : "=r"(r0), "=r"(r1), "=r"(r2), "=r"(r3) : "r"(addr));
}
__device__ __forceinline__ void mma16816(float* d, const uint32_t* a,
                                         const uint32_t* b) {
    asm volatile("mma.sync.aligned.m16n8k16.row.col.f32.f16.f16.f32 "
                 "{%0,%1,%2,%3}, {%4,%5,%6,%7}, {%8,%9}, {%0,%1,%2,%3};"
                 : "+f"(d[0]), "+f"(d[1]), "+f"(d[2]), "+f"(d[3])
                 : "r"(a[0]), "r"(a[1]), "r"(a[2]), "r"(a[3]),
                   "r"(b[0]), "r"(b[1]));
}

// ======================= prep kernels ======================================
__global__ void prep_w_all_kernel(
    const float* __restrict__ W00, const float* __restrict__ b00,
    const float* __restrict__ W10, const float* __restrict__ b10,
    const float* __restrict__ W01, const float* __restrict__ b01,
    const float* __restrict__ W11, const float* __restrict__ b11,
    const float* __restrict__ W02, const float* __restrict__ b02,
    const float* __restrict__ W12, const float* __restrict__ b12,
    __half* __restrict__ w16All, float* __restrict__ biasAll)
{
    int l = blockIdx.y;
    const float* W0 = (l == 0) ? W00 : (l == 1) ? W01 : W02;
    const float* B0 = (l == 0) ? b00 : (l == 1) ? b01 : b02;
    const float* W1 = (l == 0) ? W10 : (l == 1) ? W11 : W12;
    const float* B1 = (l == 0) ? b10 : (l == 1) ? b11 : b12;
    __half* w16 = w16All + (size_t)l * 256 * 128;
    float* biasOut = biasAll + l * 256;

    int t0 = blockIdx.x * blockDim.x + threadIdx.x;
    if (t0 < 256) biasOut[t0] = (t0 < 128) ? B0[t0] : B1[t0 - 128];
    uint32_t* wp = (uint32_t*)w16;
    for (int idx = t0; idx < 256 * 64; idx += blockDim.x * gridDim.x) {
        int n = idx >> 6, p = idx & 63;
        int k = p * 2;
        float x0, x1;
        if (n < 128) { x0 = W0[k * 128 + n]; x1 = W0[(k + 1) * 128 + n]; }
        else         { x0 = W1[k * 128 + n - 128]; x1 = W1[(k + 1) * 128 + n - 128]; }
        wp[idx] = pkh(x0, x1);
    }
}

// feat fp32 -> fp16 (coalesced float4 -> uint2)
__global__ void prep_feat_kernel(const float* __restrict__ feat,
                                 __half* __restrict__ out16, int totalQuads)
{
    int i = blockIdx.x * blockDim.x + threadIdx.x;
    if (i >= totalQuads) return;
    float4 v = __ldcs((const float4*)feat + i);
    ((uint2*)out16)[i] = make_uint2(pkh(v.x, v.y), pkh(v.z, v.w));
}

// ======================= CSR build =========================================
__global__ void zero_deg_kernel(int* deg, int n) {
    int i = blockIdx.x * blockDim.x + threadIdx.x;
    if (i < n) deg[i] = 0;
}
__global__ void count_deg_kernel(const int2* __restrict__ edges, int* deg, int E) {
    int e = blockIdx.x * blockDim.x + threadIdx.x;
    if (e >= E) return;
    int2 ed = __ldg(&edges[e]);
    atomicAdd(&deg[ed.x], 1);
    atomicAdd(&deg[ed.y], 1);
}
__global__ __launch_bounds__(1024)
void scanA_kernel(const int* __restrict__ deg, int* rowstart, int* bsum, int n) {
    __shared__ int s[1024];
    int t = threadIdx.x;
    int i = blockIdx.x * 1024 + t;
    int v = (i < n) ? deg[i] : 0;
    s[t] = v;
    __syncthreads();
#pragma unroll
    for (int o = 1; o < 1024; o <<= 1) {
        int x = (t >= o) ? s[t - o] : 0;
        __syncthreads();
        s[t] += x;
        __syncthreads();
    }
    if (i < n) rowstart[i] = s[t] - v;
    if (t == 1023) bsum[blockIdx.x] = s[1023];
}
__global__ __launch_bounds__(512)
void scanB_kernel(int* bsum, int nb) {
    __shared__ int s[512];
    int t = threadIdx.x;
    int v = (t < nb) ? bsum[t] : 0;
    s[t] = v;
    __syncthreads();
#pragma unroll
    for (int o = 1; o < 512; o <<= 1) {
        int x = (t >= o) ? s[t - o] : 0;
        __syncthreads();
        s[t] += x;
        __syncthreads();
    }
    if (t < nb) bsum[t] = s[t] - v;
}
__global__ __launch_bounds__(1024)
void scanC_kernel(int* rowstart, int* cur, const int* __restrict__ bsum,
                  int n, int total) {
    int i = blockIdx.x * 1024 + threadIdx.x;
    if (i < n) {
        int r = rowstart[i] + bsum[blockIdx.x];
        rowstart[i] = r;
        cur[i] = r;
    }
    if (i == 0) rowstart[n] = total;
}
__global__ void fill_adj_kernel(const int2* __restrict__ edges, int* cur,
                                int* adj, int E) {
    int e = blockIdx.x * blockDim.x + threadIdx.x;
    if (e >= E) return;
    int2 ed = __ldg(&edges[e]);
    int ps = atomicAdd(&cur[ed.x], 1);
    adj[ps] = ed.y;
    int pd = atomicAdd(&cur[ed.y], 1);
    adj[pd] = ed.x;
}

// ======================= persistent fp16 HMMA dual-GEMM ====================
// Tiles of 128 rows; warp grid 4(m) x 4(n); warp tile 32 x 64.
// smem: B 64K | A dbuf 2 x 32K = 128 KB.
static constexpr int SM_B     = 0;
static constexpr int SM_A     = 65536;
static constexpr int A_STRIDE = 32768;
static constexpr int SM_DYN   = 131072;

template<bool RELU>
__global__ __launch_bounds__(512, 1)
void gemm_persist_kernel(const __half* __restrict__ in,
                         const __half* __restrict__ W16,
                         const float* __restrict__ bias256,
                         __half* __restrict__ agg, __half* __restrict__ h1v,
                         int n, int numTiles)
{
    extern __shared__ char sm[];
    const uint32_t sbase = smem_to_u32(sm);
    const int tid  = threadIdx.x;
    const int wid  = tid >> 5;
    const int lane = tid & 31;

    // ---- stage B once (256 rows x 256B swizzled) ----
    {
        const uint32_t* src = (const uint32_t*)W16;
#pragma unroll
        for (int u = 0; u < 32; u++) {
            int idx = u * 512 + tid;
            int row = idx >> 6, p = idx & 63;
            uint32_t off = aswz(row, p >> 2) + (p & 3) * 4;
            *(uint32_t*)(sm + SM_B + off) = src[idx];
        }
    }

    int tile = blockIdx.x;
    if (tile >= numTiles) { __syncthreads(); return; }

    // ---- stage A tile0 into buf0 (16B loads, 16B swizzled stores) ----
    {
        int tb = tile * 128;
#pragma unroll
        for (int u = 0; u < 4; u++) {
            int idx = u * 512 + tid;           // 0..2047 uint4 slots
            int row = idx >> 4, pq = idx & 15;
            int gr = tb + row;
            uint4 v = make_uint4(0u, 0u, 0u, 0u);
            if (gr < n)
                v = __ldcs((const uint4*)(in + (size_t)gr * 128) + pq);
            if (RELU) {
                v.x = relu_h2(v.x); v.y = relu_h2(v.y);
                v.z = relu_h2(v.z); v.w = relu_h2(v.w);
            }
            *(uint4*)(sm + SM_A + aswz(row, pq)) = v;
        }
    }
    __syncthreads();

    // warp grid: 4(m) x 4(n); warp tile 32 x 64
    const int mbase = (wid & 3) * 32;
    const int nbase = (wid >> 2) * 64;
    const int aRow  = lane & 15;
    const int aKs   = lane >> 4;
    const int bTile = lane >> 3;
    const int bRow  = (lane & 7) + ((bTile >> 1) << 3);
    const int bKs   = bTile & 1;
    const int colq  = 2 * (lane & 3);

    for (int it = 0; ; it++) {
        const int buf = it & 1;
        const int tb = tile * 128;
        const int next = tile + gridDim.x;
        const bool hasNext = next < numTiles;

        // prefetch next A tile (LDG under compute)
        uint4 pf[4];
        if (hasNext) {
            int ntb = next * 128;
#pragma unroll
            for (int u = 0; u < 4; u++) {
                int idx = u * 512 + tid;
                int row = idx >> 4, pq = idx & 15;
                int gr = ntb + row;
                pf[u] = (gr < n)
                    ? __ldcs((const uint4*)(in + (size_t)gr * 128) + pq)
                    : make_uint4(0u, 0u, 0u, 0u);
            }
        }

        // ---- compute: K=128 (8 k-steps), warp tile 32x64 ----
        float d[2][8][4];
#pragma unroll
        for (int mb = 0; mb < 2; mb++)
#pragma unroll
            for (int nb = 0; nb < 8; nb++)
#pragma unroll
                for (int q = 0; q < 4; q++) d[mb][nb][q] = 0.f;

        const uint32_t aB = sbase + SM_A + buf * A_STRIDE;
        const uint32_t bB = sbase + SM_B;
#pragma unroll
        for (int kk = 0; kk < 8; kk++) {
            const int kblk0 = kk * 2;
            uint32_t a[2][4];
#pragma unroll
            for (int mb = 0; mb < 2; mb++) {
                uint32_t addr = aB + aswz(mbase + mb * 16 + aRow, kblk0 + aKs);
                ldsm_x4(a[mb][0], a[mb][1], a[mb][2], a[mb][3], addr);
            }
#pragma unroll
            for (int nb2 = 0; nb2 < 4; nb2++) {
                uint32_t addr = bB + aswz(nbase + nb2 * 16 + bRow, kblk0 + bKs);
                uint32_t b0, b1, b2, b3;
                ldsm_x4(b0, b1, b2, b3, addr);
                uint32_t blo[2] = {b0, b1};
                uint32_t bhi[2] = {b2, b3};
                mma16816(d[0][nb2 * 2 + 0], a[0], blo);
                mma16816(d[1][nb2 * 2 + 0], a[1], blo);
                mma16816(d[0][nb2 * 2 + 1], a[0], bhi);
                mma16816(d[1][nb2 * 2 + 1], a[1], bhi);
            }
        }

        // ---- epilogue: +bias; agg(h0) streamed, h1 cached (L2-resident) ----
#pragma unroll
        for (int mb = 0; mb < 2; mb++) {
#pragma unroll
            for (int h = 0; h < 2; h++) {
                int row = tb + mbase + mb * 16 + (lane >> 2) + h * 8;
                if (row >= n) continue;
#pragma unroll
                for (int nb = 0; nb < 8; nb++) {
                    int col = nbase + nb * 8 + colq;
                    float2 bv = __ldg((const float2*)(bias256 + col));
                    float vx = d[mb][nb][2 * h + 0] + bv.x;
                    float vy = d[mb][nb][2 * h + 1] + bv.y;
                    uint32_t pv = pkh(vx, vy);
                    if (col < 128)
                        __stcs((unsigned int*)(agg + (size_t)row * 128 + col), pv);
                    else
                        *(uint32_t*)(h1v + (size_t)row * 128 + (col - 128)) = pv;
                }
            }
        }

        if (!hasNext) break;

        // ---- store prefetched tile into other buffer ----
        {
            char* ab = sm + SM_A + (buf ^ 1) * A_STRIDE;
#pragma unroll
            for (int u = 0; u < 4; u++) {
                int idx = u * 512 + tid;
                int row = idx >> 4, pq = idx & 15;
                uint4 v = pf[u];
                if (RELU) {
                    v.x = relu_h2(v.x); v.y = relu_h2(v.y);
                    v.z = relu_h2(v.z); v.w = relu_h2(v.w);
                }
                *(uint4*)(ab + aswz(row, pq)) = v;
            }
        }
        tile = next;
        __syncthreads();
    }
}

// ======================= CSR gather (128-wide, fp16, L2-friendly) ==========
__global__ __launch_bounds__(256)
void gather128_kernel(const int* __restrict__ rowstart, const int* __restrict__ adj,
                      const __half* __restrict__ h1, __half* __restrict__ agg, int n)
{
    int node = blockIdx.x * 8 + (threadIdx.x >> 5);
    int lane = threadIdx.x & 31;
    if (node >= n) return;
    int rs = __ldg(&rowstart[node]);
    int re = __ldg(&rowstart[node + 1]);
    int k0 = lane * 4;
    uint2* ap = (uint2*)(agg + (size_t)node * 128 + k0);
    float4 acc = h4tof4(__ldcs(ap));

    for (int base = rs; base < re; base += 32) {
        int cnt = re - base;
        if (cnt > 32) cnt = 32;
        int aj = (lane < cnt) ? __ldg(&adj[base + lane]) : 0;
        int t = 0;
        for (; t + 3 < cnt; t += 4) {
            int j0 = __shfl_sync(0xffffffffu, aj, t);
            int j1 = __shfl_sync(0xffffffffu, aj, t + 1);
            int j2 = __shfl_sync(0xffffffffu, aj, t + 2);
            int j3 = __shfl_sync(0xffffffffu, aj, t + 3);
            float4 v0 = h4tof4(__ldg((const uint2*)(h1 + (size_t)j0 * 128 + k0)));
            float4 v1 = h4tof4(__ldg((const uint2*)(h1 + (size_t)j1 * 128 + k0)));
            float4 v2 = h4tof4(__ldg((const uint2*)(h1 + (size_t)j2 * 128 + k0)));
            float4 v3 = h4tof4(__ldg((const uint2*)(h1 + (size_t)j3 * 128 + k0)));
            acc.x += v0.x + v1.x + v2.x + v3.x;
            acc.y += v0.y + v1.y + v2.y + v3.y;
            acc.z += v0.z + v1.z + v2.z + v3.z;
            acc.w += v0.w + v1.w + v2.w + v3.w;
        }
        if (t + 1 < cnt) {
            int j0 = __shfl_sync(0xffffffffu, aj, t);
            int j1 = __shfl_sync(0xffffffffu, aj, t + 1);
            float4 v0 = h4tof4(__ldg((const uint2*)(h1 + (size_t)j0 * 128 + k0)));
            float4 v1 = h4tof4(__ldg((const uint2*)(h1 + (size_t)j1 * 128 + k0)));
            acc.x += v0.x + v1.x; acc.y += v0.y + v1.y;
            acc.z += v0.z + v1.z; acc.w += v0.w + v1.w;
            t += 2;
        }
        if (t < cnt) {
            int j = __shfl_sync(0xffffffffu, aj, t);
            float4 v = h4tof4(__ldg((const uint2*)(h1 + (size_t)j * 128 + k0)));
            acc.x += v.x; acc.y += v.y; acc.z += v.z; acc.w += v.w;
        }
    }
    __stcs(ap, f4toh4(acc));
}

// ======================= final layer (dout=3), fp16 input ===================
__global__ __launch_bounds__(256)
void final_kernel(const __half* __restrict__ in, const float* __restrict__ feat,
                  const float* __restrict__ W0, const float* __restrict__ b0,
                  const float* __restrict__ W1, const float* __restrict__ b1,
                  float* __restrict__ out, float* __restrict__ h1s, int n)
{
    __shared__ float ws[128][6];
    __shared__ float bs[6];
    int tid = threadIdx.x;
    for (int idx = tid; idx < 768; idx += 256) {
        int k = idx / 6, j = idx % 6;
        ws[k][j] = (j < 3) ? __ldg(&W0[k * 3 + j]) : __ldg(&W1[k * 3 + (j - 3)]);
    }
    if (tid < 3)      bs[tid] = __ldg(&b0[tid]);
    else if (tid < 6) bs[tid] = __ldg(&b1[tid - 3]);
    __syncthreads();

    int lane = tid & 31;
    int node = blockIdx.x * 8 + (tid >> 5);
    if (node >= n) return;

    float acc[6] = {0.f, 0.f, 0.f, 0.f, 0.f, 0.f};
    const __half* xin = in + (size_t)node * 128;
    const float*  xf  = feat + (size_t)node * 128;
#pragma unroll
    for (int f = 0; f < 4; f++) {
        int k = f * 32 + lane;
        float x = fmaxf(__half2float(xin[k]), 0.f) + xf[k];
#pragma unroll
        for (int j = 0; j < 6; j++) acc[j] += x * ws[k][j];
    }
#pragma unroll
    for (int j = 0; j < 6; j++) {
#pragma unroll
        for (int o = 16; o > 0; o >>= 1)
            acc[j] += __shfl_xor_sync(0xffffffffu, acc[j], o);
    }
    if (lane == 0) {
        out[node * 3 + 0] = acc[0] + bs[0];
        out[node * 3 + 1] = acc[1] + bs[1];
        out[node * 3 + 2] = acc[2] + bs[2];
        h1s[node * 3 + 0] = acc[3] + bs[3];
        h1s[node * 3 + 1] = acc[4] + bs[4];
        h1s[node * 3 + 2] = acc[5] + bs[5];
    }
}

__global__ void gather3_kernel(const int* __restrict__ rowstart,
                               const int* __restrict__ adj,
                               const float* __restrict__ h1s,
                               float* __restrict__ out, int n)
{
    int i = blockIdx.x * blockDim.x + threadIdx.x;
    if (i >= n) return;
    int rs = __ldg(&rowstart[i]);
    int re = __ldg(&rowstart[i + 1]);
    float a0 = 0.f, a1 = 0.f, a2 = 0.f;
    for (int e = rs; e < re; e++) {
        int j = __ldg(&adj[e]);
        a0 += __ldg(&h1s[j * 3 + 0]);
        a1 += __ldg(&h1s[j * 3 + 1]);
        a2 += __ldg(&h1s[j * 3 + 2]);
    }
    out[i * 3 + 0] += a0;
    out[i * 3 + 1] += a1;
    out[i * 3 + 2] += a2;
}

// ======================= launch ============================================
extern "C" void kernel_launch(void* const* d_in, const int* in_sizes, int n_in,
                              void* d_out, int out_size)
{
    const float* feat  = (const float*)d_in[0];
    const int2*  edges = (const int2*) d_in[1];
    const int N = in_sizes[0] / 128;
    const int E = in_sizes[1] / 2;

    const float *W0[4], *B0[4], *W1[4], *B1[4];
    for (int i = 0; i < 4; i++) {
        W0[i] = (const float*)d_in[2 + 4 * i];
        B0[i] = (const float*)d_in[3 + 4 * i];
        W1[i] = (const float*)d_in[4 + 4 * i];
        B1[i] = (const float*)d_in[5 + 4 * i];
    }

    __half *feat16, *bufA, *bufB, *h1, *w16All;
    float *h1s, *biasAll;
    int *deg, *cur, *rowstart, *adj, *bsum;
    cudaGetSymbolAddress((void**)&feat16, g_feat16);
    cudaGetSymbolAddress((void**)&bufA, g_bufA);
    cudaGetSymbolAddress((void**)&bufB, g_bufB);
    cudaGetSymbolAddress((void**)&h1,   g_h1);
    cudaGetSymbolAddress((void**)&h1s,  g_h1s);
    cudaGetSymbolAddress((void**)&w16All, g_W16);
    cudaGetSymbolAddress((void**)&biasAll, g_bias);
    cudaGetSymbolAddress((void**)&deg, g_deg);
    cudaGetSymbolAddress((void**)&cur, g_cur);
    cudaGetSymbolAddress((void**)&rowstart, g_rowstart);
    cudaGetSymbolAddress((void**)&adj, g_adj);
    cudaGetSymbolAddress((void**)&bsum, g_bsum);

    cudaFuncSetAttribute((const void*)gemm_persist_kernel<false>,
                         cudaFuncAttributeMaxDynamicSharedMemorySize, SM_DYN);
    cudaFuncSetAttribute((const void*)gemm_persist_kernel<true>,
                         cudaFuncAttributeMaxDynamicSharedMemorySize, SM_DYN);

    const int numTiles = (N + 127) / 128;
    const int PGRID = 148;
    const int gaBlocks = (N + 7) / 8;
    const int NB = (N + 1023) / 1024;
    float* out = (float*)d_out;

    // launch 0: combined weight prep
    {
        dim3 g(16, 3, 1);
        prep_w_all_kernel<<<g, 256>>>(W0[0], B0[0], W1[0], B1[0],
                                      W0[1], B0[1], W1[1], B1[1],
                                      W0[2], B0[2], W1[2], B1[2],
                                      w16All, biasAll);
    }
    // launch 1: feat -> fp16
    prep_feat_kernel<<<(N * 32 + 255) / 256, 256>>>(feat, feat16, N * 32);
    // launch 2: CSR degree zero
    zero_deg_kernel<<<(N + 255) / 256, 256>>>(deg, N);
    // launch 3: layer-0 GEMM -> ncu lands here
    gemm_persist_kernel<false><<<PGRID, 512, SM_DYN>>>(feat16, w16All, biasAll,
                                                       bufA, h1, N, numTiles);
    // launches 4-8: rest of CSR build
    count_deg_kernel<<<(E + 255) / 256, 256>>>(edges, deg, E);
    scanA_kernel<<<NB, 1024>>>(deg, rowstart, bsum, N);
    scanB_kernel<<<1, 512>>>(bsum, NB);
    scanC_kernel<<<NB, 1024>>>(rowstart, cur, bsum, N, 2 * E);
    fill_adj_kernel<<<(E + 255) / 256, 256>>>(edges, cur, adj, E);

    gather128_kernel<<<gaBlocks, 256>>>(rowstart, adj, h1, bufA, N);

    gemm_persist_kernel<true><<<PGRID, 512, SM_DYN>>>(bufA, w16All + 256 * 128,
                                                      biasAll + 256, bufB, h1, N, numTiles);
    gather128_kernel<<<gaBlocks, 256>>>(rowstart, adj, h1, bufB, N);

    gemm_persist_kernel<true><<<PGRID, 512, SM_DYN>>>(bufB, w16All + 2 * 256 * 128,
                                                      biasAll + 2 * 256, bufA, h1, N, numTiles);
    gather128_kernel<<<gaBlocks, 256>>>(rowstart, adj, h1, bufA, N);

    final_kernel<<<gaBlocks, 256>>>(bufA, feat, W0[3], B0[3], W1[3], B1[3], out, h1s, N);
    gather3_kernel<<<(N + 255) / 256, 256>>>(rowstart, adj, h1s, out, N);
}

// round 15
// speedup vs baseline: 1.0102x; 1.0102x over previous
#include <cuda_runtime.h>
#include <cuda_fp16.h>
#include <cstdint>

// ---------------------------------------------------------------------------
// MeshRefineNet on GB300 (sm_103a), R15 = R14 with B WEIGHT FRAGMENTS HOISTED
// INTO REGISTERS (loaded once per persistent CTA): inner loop is 2 LDSM + 16
// MMA per k-step (was 6 LDSM + 16 MMA) -> L1/shared pipe pressure cut ~3x.
// 256 threads, warp grid 2(m) x 4(n), warp tile 32x64, M-tile 64.
//   layer i: h0 = x@W0+b0; h1 = x@W1+b1; out = h0 + sum_{j in N(i)} h1[j]
//   relu after layers 0..2; skip before layer 3; layer 3 dout=3.
// fp16 intermediates, fp32 accumulation (rel err ~2e-4, thr 1e-3).
// ---------------------------------------------------------------------------

#define NMAX 320000
#define EMAX 1000000

__device__ __align__(16) __half g_feat16[NMAX * 128];
__device__ __align__(16) __half g_bufA[NMAX * 128];
__device__ __align__(16) __half g_bufB[NMAX * 128];
__device__ __align__(16) __half g_h1 [NMAX * 128];
__device__ float g_h1s[NMAX * 3];

__device__ __align__(16) __half g_W16[3][256 * 128];
__device__ float g_bias[3][256];

__device__ int g_deg[NMAX];
__device__ int g_cur[NMAX];
__device__ int g_rowstart[NMAX + 1];
__device__ int g_adj[2 * EMAX];
__device__ int g_bsum[512];

// ======================= helpers ===========================================
__device__ __forceinline__ uint32_t smem_to_u32(const void* p) {
    uint32_t a;
    asm("{ .reg .u64 t; cvta.to.shared.u64 t, %1; cvt.u32.u64 %0, t; }"
        : "=r"(a) : "l"(p));
    return a;
}
__device__ __forceinline__ uint32_t pkh(float a, float b) {
    __half2 t = __floats2half2_rn(a, b);
    return *(uint32_t*)&t;
}
__device__ __forceinline__ float2 uph(uint32_t u) {
    __half2 h = *(__half2*)&u;
    return __half22float2(h);
}
__device__ __forceinline__ float4 h4tof4(uint2 u) {
    float2 a = uph(u.x), b = uph(u.y);
    return make_float4(a.x, a.y, b.x, b.y);
}
__device__ __forceinline__ uint2 f4toh4(float4 v) {
    uint2 u;
    u.x = pkh(v.x, v.y);
    u.y = pkh(v.z, v.w);
    return u;
}
__device__ __forceinline__ uint32_t relu_h2(uint32_t u) {
    __half2 h = *(__half2*)&u;
    __half2 z = __floats2half2_rn(0.f, 0.f);
    h = __hmax2(h, z);
    return *(uint32_t*)&h;
}
// XOR-swizzled offset for 16-bit tile images with 256B rows (128 halves/row).
__device__ __forceinline__ uint32_t aswz(uint32_t row, uint32_t kblk) {
    return row * 256u + ((((kblk ^ row) & 7u) | (kblk & 8u)) << 4);
}
__device__ __forceinline__ void ldsm_x4(uint32_t& r0, uint32_t& r1,
                                        uint32_t& r2, uint32_t& r3, uint32_t addr) {
    asm volatile("ldmatrix.sync.aligned.m8n8.x4.shared.b16 {%0,%1,%2,%3}, [%4];"
                 : "=r"(r0), "=r"(r1), "=r"(r2), "=r"(r3) : "r"(addr));
}
__device__ __forceinline__ void mma16816(float* d, const uint32_t* a,
                                         const uint32_t* b) {
    asm volatile("mma.sync.aligned.m16n8k16.row.col.f32.f16.f16.f32 "
                 "{%0,%1,%2,%3}, {%4,%5,%6,%7}, {%8,%9}, {%0,%1,%2,%3};"
                 : "+f"(d[0]), "+f"(d[1]), "+f"(d[2]), "+f"(d[3])
                 : "r"(a[0]), "r"(a[1]), "r"(a[2]), "r"(a[3]),
                   "r"(b[0]), "r"(b[1]));
}

// ======================= prep kernels ======================================
__global__ void prep_w_all_kernel(
    const float* __restrict__ W00, const float* __restrict__ b00,
    const float* __restrict__ W10, const float* __restrict__ b10,
    const float* __restrict__ W01, const float* __restrict__ b01,
    const float* __restrict__ W11, const float* __restrict__ b11,
    const float* __restrict__ W02, const float* __restrict__ b02,
    const float* __restrict__ W12, const float* __restrict__ b12,
    __half* __restrict__ w16All, float* __restrict__ biasAll)
{
    int l = blockIdx.y;
    const float* W0 = (l == 0) ? W00 : (l == 1) ? W01 : W02;
    const float* B0 = (l == 0) ? b00 : (l == 1) ? b01 : b02;
    const float* W1 = (l == 0) ? W10 : (l == 1) ? W11 : W12;
    const float* B1 = (l == 0) ? b10 : (l == 1) ? b11 : b12;
    __half* w16 = w16All + (size_t)l * 256 * 128;
    float* biasOut = biasAll + l * 256;

    int t0 = blockIdx.x * blockDim.x + threadIdx.x;
    if (t0 < 256) biasOut[t0] = (t0 < 128) ? B0[t0] : B1[t0 - 128];
    uint32_t* wp = (uint32_t*)w16;
    for (int idx = t0; idx < 256 * 64; idx += blockDim.x * gridDim.x) {
        int n = idx >> 6, p = idx & 63;
        int k = p * 2;
        float x0, x1;
        if (n < 128) { x0 = W0[k * 128 + n]; x1 = W0[(k + 1) * 128 + n]; }
        else         { x0 = W1[k * 128 + n - 128]; x1 = W1[(k + 1) * 128 + n - 128]; }
        wp[idx] = pkh(x0, x1);
    }
}

__global__ void prep_feat_kernel(const float* __restrict__ feat,
                                 __half* __restrict__ out16, int totalQuads)
{
    int i = blockIdx.x * blockDim.x + threadIdx.x;
    if (i >= totalQuads) return;
    float4 v = __ldcs((const float4*)feat + i);
    ((uint2*)out16)[i] = make_uint2(pkh(v.x, v.y), pkh(v.z, v.w));
}

// ======================= CSR build =========================================
__global__ void zero_deg_kernel(int* deg, int n) {
    int i = blockIdx.x * blockDim.x + threadIdx.x;
    if (i < n) deg[i] = 0;
}
__global__ void count_deg_kernel(const int2* __restrict__ edges, int* deg, int E) {
    int e = blockIdx.x * blockDim.x + threadIdx.x;
    if (e >= E) return;
    int2 ed = __ldg(&edges[e]);
    atomicAdd(&deg[ed.x], 1);
    atomicAdd(&deg[ed.y], 1);
}
__global__ __launch_bounds__(1024)
void scanA_kernel(const int* __restrict__ deg, int* rowstart, int* bsum, int n) {
    __shared__ int s[1024];
    int t = threadIdx.x;
    int i = blockIdx.x * 1024 + t;
    int v = (i < n) ? deg[i] : 0;
    s[t] = v;
    __syncthreads();
#pragma unroll
    for (int o = 1; o < 1024; o <<= 1) {
        int x = (t >= o) ? s[t - o] : 0;
        __syncthreads();
        s[t] += x;
        __syncthreads();
    }
    if (i < n) rowstart[i] = s[t] - v;
    if (t == 1023) bsum[blockIdx.x] = s[1023];
}
__global__ __launch_bounds__(512)
void scanB_kernel(int* bsum, int nb) {
    __shared__ int s[512];
    int t = threadIdx.x;
    int v = (t < nb) ? bsum[t] : 0;
    s[t] = v;
    __syncthreads();
#pragma unroll
    for (int o = 1; o < 512; o <<= 1) {
        int x = (t >= o) ? s[t - o] : 0;
        __syncthreads();
        s[t] += x;
        __syncthreads();
    }
    if (t < nb) bsum[t] = s[t] - v;
}
__global__ __launch_bounds__(1024)
void scanC_kernel(int* rowstart, int* cur, const int* __restrict__ bsum,
                  int n, int total) {
    int i = blockIdx.x * 1024 + threadIdx.x;
    if (i < n) {
        int r = rowstart[i] + bsum[blockIdx.x];
        rowstart[i] = r;
        cur[i] = r;
    }
    if (i == 0) rowstart[n] = total;
}
__global__ void fill_adj_kernel(const int2* __restrict__ edges, int* cur,
                                int* adj, int E) {
    int e = blockIdx.x * blockDim.x + threadIdx.x;
    if (e >= E) return;
    int2 ed = __ldg(&edges[e]);
    int ps = atomicAdd(&cur[ed.x], 1);
    adj[ps] = ed.y;
    int pd = atomicAdd(&cur[ed.y], 1);
    adj[pd] = ed.x;
}

// ======================= persistent fp16 HMMA dual-GEMM ====================
// 256 threads; warp grid 2(m) x 4(n); warp tile 32 x 64; M-tile 64 rows.
// B fragments held in registers (loaded once). smem: B 64K | A dbuf 2x16K.
static constexpr int SM_B     = 0;
static constexpr int SM_A     = 65536;
static constexpr int A_STRIDE = 16384;
static constexpr int SM_DYN   = 98304;

template<bool RELU>
__global__ __launch_bounds__(256, 1)
void gemm_persist_kernel(const __half* __restrict__ in,
                         const __half* __restrict__ W16,
                         const float* __restrict__ bias256,
                         __half* __restrict__ agg, __half* __restrict__ h1v,
                         int n, int numTiles)
{
    extern __shared__ char sm[];
    const uint32_t sbase = smem_to_u32(sm);
    const int tid  = threadIdx.x;
    const int wid  = tid >> 5;
    const int lane = tid & 31;

    // ---- stage B once (256 rows x 256B swizzled) ----
    {
        const uint32_t* src = (const uint32_t*)W16;
#pragma unroll
        for (int u = 0; u < 64; u++) {
            int idx = u * 256 + tid;
            int row = idx >> 6, p = idx & 63;
            uint32_t off = aswz(row, p >> 2) + (p & 3) * 4;
            *(uint32_t*)(sm + SM_B + off) = src[idx];
        }
    }

    int tile = blockIdx.x;

    const int mbase = (wid & 1) * 32;
    const int nbase = (wid >> 1) * 64;
    const int aRow  = lane & 15;
    const int aKs   = lane >> 4;
    const int bTile = lane >> 3;
    const int bRow  = (lane & 7) + ((bTile >> 1) << 3);
    const int bKs   = bTile & 1;
    const int colq  = 2 * (lane & 3);

    // ---- stage A tile0 into buf0 (only if this CTA has work) ----
    if (tile < numTiles) {
        int tb = tile * 64;
#pragma unroll
        for (int u = 0; u < 4; u++) {
            int idx = u * 256 + tid;           // 0..1023 uint4 slots
            int row = idx >> 4, pq = idx & 15;
            int gr = tb + row;
            uint4 v = make_uint4(0u, 0u, 0u, 0u);
            if (gr < n)
                v = __ldcs((const uint4*)(in + (size_t)gr * 128) + pq);
            if (RELU) {
                v.x = relu_h2(v.x); v.y = relu_h2(v.y);
                v.z = relu_h2(v.z); v.w = relu_h2(v.w);
            }
            *(uint4*)(sm + SM_A + aswz(row, pq)) = v;
        }
    }
    __syncthreads();

    // ---- load ALL B fragments into registers (once per CTA) ----
    uint32_t bf[8][4][4];
    {
        const uint32_t bB = sbase + SM_B;
#pragma unroll
        for (int kk = 0; kk < 8; kk++) {
            const int kblk0 = kk * 2;
#pragma unroll
            for (int nb2 = 0; nb2 < 4; nb2++) {
                uint32_t addr = bB + aswz(nbase + nb2 * 16 + bRow, kblk0 + bKs);
                ldsm_x4(bf[kk][nb2][0], bf[kk][nb2][1],
                        bf[kk][nb2][2], bf[kk][nb2][3], addr);
            }
        }
    }

    if (tile >= numTiles) return;

    for (int it = 0; ; it++) {
        const int buf = it & 1;
        const int tb = tile * 64;
        const int next = tile + gridDim.x;
        const bool hasNext = next < numTiles;

        // prefetch next A tile (LDG under compute)
        uint4 pf[4];
        if (hasNext) {
            int ntb = next * 64;
#pragma unroll
            for (int u = 0; u < 4; u++) {
                int idx = u * 256 + tid;
                int row = idx >> 4, pq = idx & 15;
                int gr = ntb + row;
                pf[u] = (gr < n)
                    ? __ldcs((const uint4*)(in + (size_t)gr * 128) + pq)
                    : make_uint4(0u, 0u, 0u, 0u);
            }
        }

        // ---- compute: K=128 (8 k-steps), 2 LDSM + 16 MMA each ----
        float d[2][8][4];
#pragma unroll
        for (int mb = 0; mb < 2; mb++)
#pragma unroll
            for (int nb = 0; nb < 8; nb++)
#pragma unroll
                for (int q = 0; q < 4; q++) d[mb][nb][q] = 0.f;

        const uint32_t aB = sbase + SM_A + buf * A_STRIDE;
#pragma unroll
        for (int kk = 0; kk < 8; kk++) {
            const int kblk0 = kk * 2;
            uint32_t a[2][4];
#pragma unroll
            for (int mb = 0; mb < 2; mb++) {
                uint32_t addr = aB + aswz(mbase + mb * 16 + aRow, kblk0 + aKs);
                ldsm_x4(a[mb][0], a[mb][1], a[mb][2], a[mb][3], addr);
            }
#pragma unroll
            for (int nb2 = 0; nb2 < 4; nb2++) {
                uint32_t blo[2] = {bf[kk][nb2][0], bf[kk][nb2][1]};
                uint32_t bhi[2] = {bf[kk][nb2][2], bf[kk][nb2][3]};
                mma16816(d[0][nb2 * 2 + 0], a[0], blo);
                mma16816(d[1][nb2 * 2 + 0], a[1], blo);
                mma16816(d[0][nb2 * 2 + 1], a[0], bhi);
                mma16816(d[1][nb2 * 2 + 1], a[1], bhi);
            }
        }

        // ---- epilogue: +bias; agg(h0) streamed, h1 cached (L2-resident) ----
#pragma unroll
        for (int mb = 0; mb < 2; mb++) {
#pragma unroll
            for (int h = 0; h < 2; h++) {
                int row = tb + mbase + mb * 16 + (lane >> 2) + h * 8;
                if (row >= n) continue;
#pragma unroll
                for (int nb = 0; nb < 8; nb++) {
                    int col = nbase + nb * 8 + colq;
                    float2 bv = __ldg((const float2*)(bias256 + col));
                    float vx = d[mb][nb][2 * h + 0] + bv.x;
                    float vy = d[mb][nb][2 * h + 1] + bv.y;
                    uint32_t pv = pkh(vx, vy);
                    if (col < 128)
                        __stcs((unsigned int*)(agg + (size_t)row * 128 + col), pv);
                    else
                        *(uint32_t*)(h1v + (size_t)row * 128 + (col - 128)) = pv;
                }
            }
        }

        if (!hasNext) break;

        // ---- store prefetched tile into other buffer ----
        {
            char* ab = sm + SM_A + (buf ^ 1) * A_STRIDE;
#pragma unroll
            for (int u = 0; u < 4; u++) {
                int idx = u * 256 + tid;
                int row = idx >> 4, pq = idx & 15;
                uint4 v = pf[u];
                if (RELU) {
                    v.x = relu_h2(v.x); v.y = relu_h2(v.y);
                    v.z = relu_h2(v.z); v.w = relu_h2(v.w);
                }
                *(uint4*)(ab + aswz(row, pq)) = v;
            }
        }
        tile = next;
        __syncthreads();
    }
}

// ======================= CSR gather (128-wide, fp16, L2-friendly) ==========
__global__ __launch_bounds__(256)
void gather128_kernel(const int* __restrict__ rowstart, const int* __restrict__ adj,
                      const __half* __restrict__ h1, __half* __restrict__ agg, int n)
{
    int node = blockIdx.x * 8 + (threadIdx.x >> 5);
    int lane = threadIdx.x & 31;
    if (node >= n) return;
    int rs = __ldg(&rowstart[node]);
    int re = __ldg(&rowstart[node + 1]);
    int k0 = lane * 4;
    uint2* ap = (uint2*)(agg + (size_t)node * 128 + k0);
    float4 acc = h4tof4(__ldcs(ap));

    for (int base = rs; base < re; base += 32) {
        int cnt = re - base;
        if (cnt > 32) cnt = 32;
        int aj = (lane < cnt) ? __ldg(&adj[base + lane]) : 0;
        int t = 0;
        for (; t + 3 < cnt; t += 4) {
            int j0 = __shfl_sync(0xffffffffu, aj, t);
            int j1 = __shfl_sync(0xffffffffu, aj, t + 1);
            int j2 = __shfl_sync(0xffffffffu, aj, t + 2);
            int j3 = __shfl_sync(0xffffffffu, aj, t + 3);
            float4 v0 = h4tof4(__ldg((const uint2*)(h1 + (size_t)j0 * 128 + k0)));
            float4 v1 = h4tof4(__ldg((const uint2*)(h1 + (size_t)j1 * 128 + k0)));
            float4 v2 = h4tof4(__ldg((const uint2*)(h1 + (size_t)j2 * 128 + k0)));
            float4 v3 = h4tof4(__ldg((const uint2*)(h1 + (size_t)j3 * 128 + k0)));
            acc.x += v0.x + v1.x + v2.x + v3.x;
            acc.y += v0.y + v1.y + v2.y + v3.y;
            acc.z += v0.z + v1.z + v2.z + v3.z;
            acc.w += v0.w + v1.w + v2.w + v3.w;
        }
        if (t + 1 < cnt) {
            int j0 = __shfl_sync(0xffffffffu, aj, t);
            int j1 = __shfl_sync(0xffffffffu, aj, t + 1);
            float4 v0 = h4tof4(__ldg((const uint2*)(h1 + (size_t)j0 * 128 + k0)));
            float4 v1 = h4tof4(__ldg((const uint2*)(h1 + (size_t)j1 * 128 + k0)));
            acc.x += v0.x + v1.x; acc.y += v0.y + v1.y;
            acc.z += v0.z + v1.z; acc.w += v0.w + v1.w;
            t += 2;
        }
        if (t < cnt) {
            int j = __shfl_sync(0xffffffffu, aj, t);
            float4 v = h4tof4(__ldg((const uint2*)(h1 + (size_t)j * 128 + k0)));
            acc.x += v.x; acc.y += v.y; acc.z += v.z; acc.w += v.w;
        }
    }
    __stcs(ap, f4toh4(acc));
}

// ======================= final layer (dout=3), fp16 input ===================
__global__ __launch_bounds__(256)
void final_kernel(const __half* __restrict__ in, const float* __restrict__ feat,
                  const float* __restrict__ W0, const float* __restrict__ b0,
                  const float* __restrict__ W1, const float* __restrict__ b1,
                  float* __restrict__ out, float* __restrict__ h1s, int n)
{
    __shared__ float ws[128][6];
    __shared__ float bs[6];
    int tid = threadIdx.x;
    for (int idx = tid; idx < 768; idx += 256) {
        int k = idx / 6, j = idx % 6;
        ws[k][j] = (j < 3) ? __ldg(&W0[k * 3 + j]) : __ldg(&W1[k * 3 + (j - 3)]);
    }
    if (tid < 3)      bs[tid] = __ldg(&b0[tid]);
    else if (tid < 6) bs[tid] = __ldg(&b1[tid - 3]);
    __syncthreads();

    int lane = tid & 31;
    int node = blockIdx.x * 8 + (tid >> 5);
    if (node >= n) return;

    float acc[6] = {0.f, 0.f, 0.f, 0.f, 0.f, 0.f};
    const __half* xin = in + (size_t)node * 128;
    const float*  xf  = feat + (size_t)node * 128;
#pragma unroll
    for (int f = 0; f < 4; f++) {
        int k = f * 32 + lane;
        float x = fmaxf(__half2float(xin[k]), 0.f) + xf[k];
#pragma unroll
        for (int j = 0; j < 6; j++) acc[j] += x * ws[k][j];
    }
#pragma unroll
    for (int j = 0; j < 6; j++) {
#pragma unroll
        for (int o = 16; o > 0; o >>= 1)
            acc[j] += __shfl_xor_sync(0xffffffffu, acc[j], o);
    }
    if (lane == 0) {
        out[node * 3 + 0] = acc[0] + bs[0];
        out[node * 3 + 1] = acc[1] + bs[1];
        out[node * 3 + 2] = acc[2] + bs[2];
        h1s[node * 3 + 0] = acc[3] + bs[3];
        h1s[node * 3 + 1] = acc[4] + bs[4];
        h1s[node * 3 + 2] = acc[5] + bs[5];
    }
}

__global__ void gather3_kernel(const int* __restrict__ rowstart,
                               const int* __restrict__ adj,
                               const float* __restrict__ h1s,
                               float* __restrict__ out, int n)
{
    int i = blockIdx.x * blockDim.x + threadIdx.x;
    if (i >= n) return;
    int rs = __ldg(&rowstart[i]);
    int re = __ldg(&rowstart[i + 1]);
    float a0 = 0.f, a1 = 0.f, a2 = 0.f;
    for (int e = rs; e < re; e++) {
        int j = __ldg(&adj[e]);
        a0 += __ldg(&h1s[j * 3 + 0]);
        a1 += __ldg(&h1s[j * 3 + 1]);
        a2 += __ldg(&h1s[j * 3 + 2]);
    }
    out[i * 3 + 0] += a0;
    out[i * 3 + 1] += a1;
    out[i * 3 + 2] += a2;
}

// ======================= launch ============================================
extern "C" void kernel_launch(void* const* d_in, const int* in_sizes, int n_in,
                              void* d_out, int out_size)
{
    const float* feat  = (const float*)d_in[0];
    const int2*  edges = (const int2*) d_in[1];
    const int N = in_sizes[0] / 128;
    const int E = in_sizes[1] / 2;

    const float *W0[4], *B0[4], *W1[4], *B1[4];
    for (int i = 0; i < 4; i++) {
        W0[i] = (const float*)d_in[2 + 4 * i];
        B0[i] = (const float*)d_in[3 + 4 * i];
        W1[i] = (const float*)d_in[4 + 4 * i];
        B1[i] = (const float*)d_in[5 + 4 * i];
    }

    __half *feat16, *bufA, *bufB, *h1, *w16All;
    float *h1s, *biasAll;
    int *deg, *cur, *rowstart, *adj, *bsum;
    cudaGetSymbolAddress((void**)&feat16, g_feat16);
    cudaGetSymbolAddress((void**)&bufA, g_bufA);
    cudaGetSymbolAddress((void**)&bufB, g_bufB);
    cudaGetSymbolAddress((void**)&h1,   g_h1);
    cudaGetSymbolAddress((void**)&h1s,  g_h1s);
    cudaGetSymbolAddress((void**)&w16All, g_W16);
    cudaGetSymbolAddress((void**)&biasAll, g_bias);
    cudaGetSymbolAddress((void**)&deg, g_deg);
    cudaGetSymbolAddress((void**)&cur, g_cur);
    cudaGetSymbolAddress((void**)&rowstart, g_rowstart);
    cudaGetSymbolAddress((void**)&adj, g_adj);
    cudaGetSymbolAddress((void**)&bsum, g_bsum);

    cudaFuncSetAttribute((const void*)gemm_persist_kernel<false>,
                         cudaFuncAttributeMaxDynamicSharedMemorySize, SM_DYN);
    cudaFuncSetAttribute((const void*)gemm_persist_kernel<true>,
                         cudaFuncAttributeMaxDynamicSharedMemorySize, SM_DYN);

    const int numTiles = (N + 63) / 64;
    const int PGRID = 148;
    const int gaBlocks = (N + 7) / 8;
    const int NB = (N + 1023) / 1024;
    float* out = (float*)d_out;

    // launch 0: combined weight prep
    {
        dim3 g(16, 3, 1);
        prep_w_all_kernel<<<g, 256>>>(W0[0], B0[0], W1[0], B1[0],
                                      W0[1], B0[1], W1[1], B1[1],
                                      W0[2], B0[2], W1[2], B1[2],
                                      w16All, biasAll);
    }
    // launch 1: feat -> fp16
    prep_feat_kernel<<<(N * 32 + 255) / 256, 256>>>(feat, feat16, N * 32);
    // launch 2: CSR degree zero
    zero_deg_kernel<<<(N + 255) / 256, 256>>>(deg, N);
    // launch 3: layer-0 GEMM -> ncu lands here
    gemm_persist_kernel<false><<<PGRID, 256, SM_DYN>>>(feat16, w16All, biasAll,
                                                       bufA, h1, N, numTiles);
    // launches 4-8: rest of CSR build
    count_deg_kernel<<<(E + 255) / 256, 256>>>(edges, deg, E);
    scanA_kernel<<<NB, 1024>>>(deg, rowstart, bsum, N);
    scanB_kernel<<<1, 512>>>(bsum, NB);
    scanC_kernel<<<NB, 1024>>>(rowstart, cur, bsum, N, 2 * E);
    fill_adj_kernel<<<(E + 255) / 256, 256>>>(edges, cur, adj, E);

    gather128_kernel<<<gaBlocks, 256>>>(rowstart, adj, h1, bufA, N);

    gemm_persist_kernel<true><<<PGRID, 256, SM_DYN>>>(bufA, w16All + 256 * 128,
                                                      biasAll + 256, bufB, h1, N, numTiles);
    gather128_kernel<<<gaBlocks, 256>>>(rowstart, adj, h1, bufB, N);

    gemm_persist_kernel<true><<<PGRID, 256, SM_DYN>>>(bufB, w16All + 2 * 256 * 128,
                                                      biasAll + 2 * 256, bufA, h1, N, numTiles);
    gather128_kernel<<<gaBlocks, 256>>>(rowstart, adj, h1, bufA, N);

    final_kernel<<<gaBlocks, 256>>>(bufA, feat, W0[3], B0[3], W1[3], B1[3], out, h1s, N);
    gather3_kernel<<<(N + 255) / 256, 256>>>(rowstart, adj, h1s, out, N);
}